// round 4
// baseline (speedup 1.0000x reference)
#include <cuda_runtime.h>

#define NN 2048
#define OUTC 16
#define STATS_BLOCKS 256
#define ROWS_PER_BLK 8

// ---- scratch (device globals; zero-initialized at load, restored to zero
//      by the last block each call so graph replays are deterministic) ----
__device__ float g_colacc[NN];          // atomic accumulator (reset each call)
__device__ float g_rowsum[NN];
__device__ float g_diag[NN];
__device__ float g_Rf[NN * OUTC];       // per-i vector (incl. trace/totsum terms)
__device__ float g_Cc[NN * OUTC];       // per-j vector
__device__ float g_Dd[NN * OUTC];       // diagonal extras
__device__ unsigned g_ctr;              // arrival counter (reset each call)

// ---------------------------------------------------------------------------
// One fused stats kernel: rowsum/colsum/diag + last block does trace/totsum,
// Rf/Cc/Dd precompute, and resets accumulators for the next graph replay.
__global__ __launch_bounds__(256) void k_stats(const float* __restrict__ A,
                                               const float* __restrict__ W) {
    __shared__ float sred[ROWS_PER_BLK][8];
    __shared__ float sW[240];
    __shared__ float sr8[8], ss8[8];
    __shared__ float s_tr, s_ts;
    __shared__ int s_last;

    int t = threadIdx.x, lane = t & 31, w = t >> 5;
    int r0 = blockIdx.x * ROWS_PER_BLK;

    float4 ca0 = make_float4(0.f, 0.f, 0.f, 0.f);
    float4 ca1 = make_float4(0.f, 0.f, 0.f, 0.f);

    #pragma unroll
    for (int r = 0; r < ROWS_PER_BLK; r++) {
        const float4* row = (const float4*)(A + (size_t)(r0 + r) * NN);
        float4 v0 = row[t];         // cols 4t   .. 4t+3
        float4 v1 = row[t + 256];   // cols 1024+4t ..
        ca0.x += v0.x; ca0.y += v0.y; ca0.z += v0.z; ca0.w += v0.w;
        ca1.x += v1.x; ca1.y += v1.y; ca1.z += v1.z; ca1.w += v1.w;
        float rs = (v0.x + v0.y) + (v0.z + v0.w) + (v1.x + v1.y) + (v1.z + v1.w);
        #pragma unroll
        for (int off = 16; off; off >>= 1) rs += __shfl_xor_sync(0xffffffffu, rs, off);
        if (lane == 0) sred[r][w] = rs;
    }

    // column partials -> global atomic accumulator (spread addresses, RED)
    atomicAdd(&g_colacc[4 * t + 0], ca0.x);
    atomicAdd(&g_colacc[4 * t + 1], ca0.y);
    atomicAdd(&g_colacc[4 * t + 2], ca0.z);
    atomicAdd(&g_colacc[4 * t + 3], ca0.w);
    atomicAdd(&g_colacc[1024 + 4 * t + 0], ca1.x);
    atomicAdd(&g_colacc[1024 + 4 * t + 1], ca1.y);
    atomicAdd(&g_colacc[1024 + 4 * t + 2], ca1.z);
    atomicAdd(&g_colacc[1024 + 4 * t + 3], ca1.w);

    __syncthreads();
    if (t < ROWS_PER_BLK) {
        float s = 0.f;
        #pragma unroll
        for (int q = 0; q < 8; q++) s += sred[t][q];
        g_rowsum[r0 + t] = s;
        g_diag[r0 + t]   = A[(size_t)(r0 + t) * NN + (r0 + t)];
    }

    // release: make this block's writes visible, then arrive
    __threadfence();
    __syncthreads();
    if (t == 0) s_last = (atomicAdd(&g_ctr, 1) == STATS_BLOCKS - 1);
    __syncthreads();
    if (!s_last) return;

    // ---- last block only: acquire, then finalize ----
    __threadfence();

    if (t < 240) sW[t] = W[t];

    float tr = 0.f, ts = 0.f;
    for (int k = t; k < NN; k += 256) { tr += g_diag[k]; ts += g_rowsum[k]; }
    #pragma unroll
    for (int off = 16; off; off >>= 1) {
        tr += __shfl_xor_sync(0xffffffffu, tr, off);
        ts += __shfl_xor_sync(0xffffffffu, ts, off);
    }
    if (lane == 0) { sr8[w] = tr; ss8[w] = ts; }
    __syncthreads();
    if (t == 0) {
        float a = 0.f, b = 0.f;
        #pragma unroll
        for (int q = 0; q < 8; q++) { a += sr8[q]; b += ss8[q]; }
        s_tr = a; s_ts = b;
    }
    __syncthreads();
    float trv = s_tr, tsv = s_ts;

    for (int i = t; i < NN; i += 256) {
        float di = g_diag[i], ri = g_rowsum[i], ci = g_colacc[i];
        g_colacc[i] = 0.f;                       // reset for next replay
        #pragma unroll
        for (int o = 0; o < OUTC; o++) {
            g_Rf[i * OUTC + o] = fmaf(di, sW[8*16+o], fmaf(ri, sW[9*16+o],
                                 fmaf(ci, sW[10*16+o], fmaf(trv, sW[13*16+o], tsv * sW[14*16+o]))));
            g_Cc[i * OUTC + o] = fmaf(di, sW[5*16+o], fmaf(ri, sW[6*16+o], ci * sW[7*16+o]));
            g_Dd[i * OUTC + o] = fmaf(di, sW[0*16+o], fmaf(ri, sW[1*16+o],
                                 fmaf(ci, sW[2*16+o], fmaf(trv, sW[3*16+o], tsv * sW[4*16+o]))));
        }
    }
    if (t == 0) g_ctr = 0;                       // reset counter for next replay
}

// ---------------------------------------------------------------------------
__device__ __forceinline__ float4 f4add(float4 a, float4 b) {
    return make_float4(a.x + b.x, a.y + b.y, a.z + b.z, a.w + b.w);
}
__device__ __forceinline__ float4 f4fma(float s, float4 w, float4 acc) {
    return make_float4(fmaf(s, w.x, acc.x), fmaf(s, w.y, acc.y),
                       fmaf(s, w.z, acc.z), fmaf(s, w.w, acc.w));
}

// 32x32 output tile per block. A^T via padded smem tile; A direct coalesced.
__global__ __launch_bounds__(256) void k_main(const float* __restrict__ A,
                                              const float* __restrict__ W,
                                              float* __restrict__ out) {
    __shared__ float sB[32][33];
    int t = threadIdx.x;
    int j0 = blockIdx.x * 32, i0 = blockIdx.y * 32;

    // transposed-source tile: rows j0..j0+31, cols i0..i0+31 (coalesced)
    #pragma unroll
    for (int k = 0; k < 4; k++) {
        int e = t + 256 * k;
        int r = e >> 5, c = e & 31;
        sB[r][c] = A[(size_t)(j0 + r) * NN + i0 + c];
    }
    __syncthreads();

    int jj = t & 31, wi = t >> 5;
    int j = j0 + jj;

    const float4* Cc4 = (const float4*)(g_Cc + (size_t)j * OUTC);
    float4 c0 = Cc4[0], c1 = Cc4[1], c2 = Cc4[2], c3 = Cc4[3];
    const float4* w11 = (const float4*)(W + 11 * 16);
    const float4* w12 = (const float4*)(W + 12 * 16);
    float4 b0 = w11[0], b1 = w11[1], b2 = w11[2], b3 = w11[3];
    float4 a0 = w12[0], a1 = w12[1], a2 = w12[2], a3 = w12[3];

    #pragma unroll
    for (int k = 0; k < 4; k++) {
        int ii = wi * 4 + k;
        int i  = i0 + ii;
        float av = A[(size_t)i * NN + j];      // coalesced across lanes
        float tv = sB[jj][ii];                 // A[j][i], conflict-free (stride 33)

        const float4* Rf4 = (const float4*)(g_Rf + (size_t)i * OUTC);
        float4 o0 = f4fma(av, a0, f4fma(tv, b0, f4add(Rf4[0], c0)));
        float4 o1 = f4fma(av, a1, f4fma(tv, b1, f4add(Rf4[1], c1)));
        float4 o2 = f4fma(av, a2, f4fma(tv, b2, f4add(Rf4[2], c2)));
        float4 o3 = f4fma(av, a3, f4fma(tv, b3, f4add(Rf4[3], c3)));

        if (i == j) {   // diagonal extras (only diagonal blocks diverge)
            const float4* Dd4 = (const float4*)(g_Dd + (size_t)i * OUTC);
            o0 = f4add(o0, Dd4[0]);
            o1 = f4add(o1, Dd4[1]);
            o2 = f4add(o2, Dd4[2]);
            o3 = f4add(o3, Dd4[3]);
        }

        float4* op = (float4*)(out + ((size_t)i * NN + j) * OUTC);
        op[0] = o0; op[1] = o1; op[2] = o2; op[3] = o3;
    }
}

extern "C" void kernel_launch(void* const* d_in, const int* in_sizes, int n_in,
                              void* d_out, int out_size) {
    const float* A = (const float*)d_in[0];
    const float* W = (const float*)d_in[1];
    float* out = (float*)d_out;

    k_stats<<<STATS_BLOCKS, 256>>>(A, W);
    k_main<<<dim3(64, 64), 256>>>(A, W, out);
}

// round 5
// speedup vs baseline: 1.4649x; 1.4649x over previous
#include <cuda_runtime.h>

#define NN 2048
#define OUTC 16

// ---- scratch (device globals; every word overwritten each call, no atomics) ----
__device__ float g_rowsum[NN];
__device__ float g_colsum[NN];
__device__ float g_diag[NN];
__device__ float g_Rf[NN * OUTC];     // per-i vector (incl. trace/totsum terms)
__device__ float g_Cc[NN * OUTC];     // per-j vector
__device__ float g_Dd[NN * OUTC];     // diagonal extras

// ---------------------------------------------------------------------------
// rowsum + diag: 256 blocks x 256 thr, 8 exclusive rows per block, float4 reads.
__global__ __launch_bounds__(256) void k_row(const float* __restrict__ A) {
    __shared__ float sred[8][8];
    int t = threadIdx.x, lane = t & 31, w = t >> 5;
    int r0 = blockIdx.x * 8;
    #pragma unroll
    for (int r = 0; r < 8; r++) {
        const float4* row = (const float4*)(A + (size_t)(r0 + r) * NN);
        float4 v0 = row[t];
        float4 v1 = row[t + 256];
        float rs = (v0.x + v0.y) + (v0.z + v0.w) + (v1.x + v1.y) + (v1.z + v1.w);
        #pragma unroll
        for (int off = 16; off; off >>= 1) rs += __shfl_xor_sync(0xffffffffu, rs, off);
        if (lane == 0) sred[r][w] = rs;
    }
    __syncthreads();
    if (t < 8) {
        float s = 0.f;
        #pragma unroll
        for (int q = 0; q < 8; q++) s += sred[t][q];
        g_rowsum[r0 + t] = s;
        g_diag[r0 + t]   = A[(size_t)(r0 + t) * NN + (r0 + t)];
    }
}

// colsum: 64 blocks x 512 thr; block owns 32 columns, no atomics.
__global__ __launch_bounds__(512) void k_col(const float* __restrict__ A) {
    __shared__ float sc[16][32];
    int t = threadIdx.x, lane = t & 31, w = t >> 5;   // 16 warps
    int j0 = blockIdx.x * 32;
    float a0 = 0.f, a1 = 0.f, a2 = 0.f, a3 = 0.f;
    for (int r = w; r < NN; r += 64) {                // 32 iters, 4 indep loads each
        a0 += A[(size_t)(r)      * NN + j0 + lane];
        a1 += A[(size_t)(r + 16) * NN + j0 + lane];
        a2 += A[(size_t)(r + 32) * NN + j0 + lane];
        a3 += A[(size_t)(r + 48) * NN + j0 + lane];
    }
    sc[w][lane] = (a0 + a1) + (a2 + a3);
    __syncthreads();
    if (t < 32) {
        float s = 0.f;
        #pragma unroll
        for (int q = 0; q < 16; q++) s += sc[q][t];
        g_colsum[j0 + t] = s;
    }
}

// precompute Rf/Cc/Dd: 32 blocks x 256. Each block redundantly reduces
// trace/totsum (cheap), then threads write float4 chunks.
__global__ __launch_bounds__(256) void k_pre(const float* __restrict__ W) {
    __shared__ float sr8[8], ss8[8];
    __shared__ float s_sc[2];
    int t = threadIdx.x, lane = t & 31, w = t >> 5;

    float tr = 0.f, ts = 0.f;
    #pragma unroll
    for (int q = 0; q < 8; q++) {
        tr += g_diag[t + 256 * q];
        ts += g_rowsum[t + 256 * q];
    }
    #pragma unroll
    for (int off = 16; off; off >>= 1) {
        tr += __shfl_xor_sync(0xffffffffu, tr, off);
        ts += __shfl_xor_sync(0xffffffffu, ts, off);
    }
    if (lane == 0) { sr8[w] = tr; ss8[w] = ts; }
    __syncthreads();
    if (t == 0) {
        float a = 0.f, b = 0.f;
        #pragma unroll
        for (int q = 0; q < 8; q++) { a += sr8[q]; b += ss8[q]; }
        s_sc[0] = a; s_sc[1] = b;
    }
    __syncthreads();
    float trv = s_sc[0], tsv = s_sc[1];

    // thread -> (i, float4 chunk): 64 i's per block, 4 chunks per i
    int il = t >> 2, c4 = t & 3;
    int i = blockIdx.x * 64 + il;
    float di = g_diag[i], ri = g_rowsum[i], ci = g_colsum[i];

    float4 w0  = *(const float4*)(W + 0*16  + c4*4);
    float4 w1  = *(const float4*)(W + 1*16  + c4*4);
    float4 w2  = *(const float4*)(W + 2*16  + c4*4);
    float4 w3  = *(const float4*)(W + 3*16  + c4*4);
    float4 w4  = *(const float4*)(W + 4*16  + c4*4);
    float4 w5  = *(const float4*)(W + 5*16  + c4*4);
    float4 w6  = *(const float4*)(W + 6*16  + c4*4);
    float4 w7  = *(const float4*)(W + 7*16  + c4*4);
    float4 w8  = *(const float4*)(W + 8*16  + c4*4);
    float4 w9  = *(const float4*)(W + 9*16  + c4*4);
    float4 w10 = *(const float4*)(W + 10*16 + c4*4);
    float4 w13 = *(const float4*)(W + 13*16 + c4*4);
    float4 w14 = *(const float4*)(W + 14*16 + c4*4);

    float4 rf, cc, dd;
    rf.x = fmaf(di,w8.x, fmaf(ri,w9.x, fmaf(ci,w10.x, fmaf(trv,w13.x, tsv*w14.x))));
    rf.y = fmaf(di,w8.y, fmaf(ri,w9.y, fmaf(ci,w10.y, fmaf(trv,w13.y, tsv*w14.y))));
    rf.z = fmaf(di,w8.z, fmaf(ri,w9.z, fmaf(ci,w10.z, fmaf(trv,w13.z, tsv*w14.z))));
    rf.w = fmaf(di,w8.w, fmaf(ri,w9.w, fmaf(ci,w10.w, fmaf(trv,w13.w, tsv*w14.w))));
    cc.x = fmaf(di,w5.x, fmaf(ri,w6.x, ci*w7.x));
    cc.y = fmaf(di,w5.y, fmaf(ri,w6.y, ci*w7.y));
    cc.z = fmaf(di,w5.z, fmaf(ri,w6.z, ci*w7.z));
    cc.w = fmaf(di,w5.w, fmaf(ri,w6.w, ci*w7.w));
    dd.x = fmaf(di,w0.x, fmaf(ri,w1.x, fmaf(ci,w2.x, fmaf(trv,w3.x, tsv*w4.x))));
    dd.y = fmaf(di,w0.y, fmaf(ri,w1.y, fmaf(ci,w2.y, fmaf(trv,w3.y, tsv*w4.y))));
    dd.z = fmaf(di,w0.z, fmaf(ri,w1.z, fmaf(ci,w2.z, fmaf(trv,w3.z, tsv*w4.z))));
    dd.w = fmaf(di,w0.w, fmaf(ri,w1.w, fmaf(ci,w2.w, fmaf(trv,w3.w, tsv*w4.w))));

    *(float4*)(g_Rf + i*OUTC + c4*4) = rf;
    *(float4*)(g_Cc + i*OUTC + c4*4) = cc;
    *(float4*)(g_Dd + i*OUTC + c4*4) = dd;
}

// ---------------------------------------------------------------------------
__device__ __forceinline__ float4 f4add(float4 a, float4 b) {
    return make_float4(a.x + b.x, a.y + b.y, a.z + b.z, a.w + b.w);
}
__device__ __forceinline__ float4 f4fma(float s, float4 w, float4 acc) {
    return make_float4(fmaf(s, w.x, acc.x), fmaf(s, w.y, acc.y),
                       fmaf(s, w.z, acc.z), fmaf(s, w.w, acc.w));
}

// 32x32 output tile per block; w in shared, interleaved compute/store to
// shrink register live ranges (target >=4 blocks/SM).
__global__ __launch_bounds__(256, 4) void k_main(const float* __restrict__ A,
                                                 const float* __restrict__ W,
                                                 float* __restrict__ out) {
    __shared__ float sB[32][33];
    __shared__ float4 sw11[4], sw12[4];
    int t = threadIdx.x;
    int j0 = blockIdx.x * 32, i0 = blockIdx.y * 32;

    if (t < 4)           sw11[t]     = *(const float4*)(W + 11*16 + t*4);
    else if (t < 8)      sw12[t - 4] = *(const float4*)(W + 12*16 + (t-4)*4);

    // transposed-source tile: rows j0..j0+31, cols i0..i0+31 (coalesced)
    #pragma unroll
    for (int k = 0; k < 4; k++) {
        int e = t + 256 * k;
        int r = e >> 5, c = e & 31;
        sB[r][c] = A[(size_t)(j0 + r) * NN + i0 + c];
    }
    __syncthreads();

    int jj = t & 31, wi = t >> 5;
    int j = j0 + jj;

    const float4* Cc4 = (const float4*)(g_Cc + (size_t)j * OUTC);
    float4 c0 = Cc4[0], c1 = Cc4[1], c2 = Cc4[2], c3 = Cc4[3];

    // batch the 8 scalar operand loads up front (MLP)
    float av[4], tv[4];
    #pragma unroll
    for (int k = 0; k < 4; k++) {
        av[k] = A[(size_t)(i0 + wi*4 + k) * NN + j];
        tv[k] = sB[jj][wi*4 + k];
    }

    #pragma unroll
    for (int k = 0; k < 4; k++) {
        int i = i0 + wi*4 + k;
        const float4* Rf4 = (const float4*)(g_Rf + (size_t)i * OUTC);
        const float4* Dd4 = (const float4*)(g_Dd + (size_t)i * OUTC);
        float4* op = (float4*)(out + ((size_t)i * NN + j) * OUTC);
        bool dg = (i == j);

        float4 o;
        o = f4fma(av[k], sw12[0], f4fma(tv[k], sw11[0], f4add(Rf4[0], c0)));
        if (dg) o = f4add(o, Dd4[0]);
        op[0] = o;
        o = f4fma(av[k], sw12[1], f4fma(tv[k], sw11[1], f4add(Rf4[1], c1)));
        if (dg) o = f4add(o, Dd4[1]);
        op[1] = o;
        o = f4fma(av[k], sw12[2], f4fma(tv[k], sw11[2], f4add(Rf4[2], c2)));
        if (dg) o = f4add(o, Dd4[2]);
        op[2] = o;
        o = f4fma(av[k], sw12[3], f4fma(tv[k], sw11[3], f4add(Rf4[3], c3)));
        if (dg) o = f4add(o, Dd4[3]);
        op[3] = o;
    }
}

extern "C" void kernel_launch(void* const* d_in, const int* in_sizes, int n_in,
                              void* d_out, int out_size) {
    const float* A = (const float*)d_in[0];
    const float* W = (const float*)d_in[1];
    float* out = (float*)d_out;

    k_row<<<256, 256>>>(A);
    k_col<<<64, 512>>>(A);
    k_pre<<<32, 256>>>(W);
    k_main<<<dim3(64, 64), 256>>>(A, W, out);
}

// round 8
// speedup vs baseline: 2.4264x; 1.6563x over previous
#include <cuda_runtime.h>

#define NN 2048
#define OUTC 16

// ---- scratch (device globals; every word overwritten each call, no atomics) ----
__device__ float g_rowsum[NN];
__device__ float g_colsum[NN];
__device__ float g_diag[NN];
__device__ float g_Rf[NN * OUTC];     // per-i vector (incl. trace/totsum terms)
__device__ float g_Cc[NN * OUTC];     // per-j vector
__device__ float g_Dd[NN * OUTC];     // diagonal extras

// ---------------------------------------------------------------------------
// Fused rowsum/diag + colsum in ONE launch (blocks 0..255 rows, 256..319 cols)
__global__ __launch_bounds__(256) void k_rowcol(const float* __restrict__ A) {
    int t = threadIdx.x, lane = t & 31, w = t >> 5;
    if (blockIdx.x < 256) {
        // ---- 8 exclusive rows per block, float4 reads ----
        __shared__ float sred[8][8];
        int r0 = blockIdx.x * 8;
        #pragma unroll
        for (int r = 0; r < 8; r++) {
            const float4* row = (const float4*)(A + (size_t)(r0 + r) * NN);
            float4 v0 = row[t];
            float4 v1 = row[t + 256];
            float rs = (v0.x + v0.y) + (v0.z + v0.w) + (v1.x + v1.y) + (v1.z + v1.w);
            #pragma unroll
            for (int off = 16; off; off >>= 1) rs += __shfl_xor_sync(0xffffffffu, rs, off);
            if (lane == 0) sred[r][w] = rs;
        }
        __syncthreads();
        if (t < 8) {
            float s = 0.f;
            #pragma unroll
            for (int q = 0; q < 8; q++) s += sred[t][q];
            g_rowsum[r0 + t] = s;
            g_diag[r0 + t]   = A[(size_t)(r0 + t) * NN + (r0 + t)];
        }
    } else {
        // ---- 32 exclusive columns per block, 4 indep accumulators ----
        __shared__ float sc[8][32];
        int j0 = (blockIdx.x - 256) * 32;
        float a0 = 0.f, a1 = 0.f, a2 = 0.f, a3 = 0.f;
        for (int r = w; r < NN; r += 32) {
            a0 += A[(size_t)(r)      * NN + j0 + lane];
            a1 += A[(size_t)(r + 8)  * NN + j0 + lane];
            a2 += A[(size_t)(r + 16) * NN + j0 + lane];
            a3 += A[(size_t)(r + 24) * NN + j0 + lane];
        }
        sc[w][lane] = (a0 + a1) + (a2 + a3);
        __syncthreads();
        if (t < 32) {
            float s = 0.f;
            #pragma unroll
            for (int q = 0; q < 8; q++) s += sc[q][t];
            g_colsum[j0 + t] = s;
        }
    }
}

// precompute Rf/Cc/Dd: 32 blocks x 256. Each block redundantly reduces
// trace/totsum (cheap), then threads write float4 chunks.
__global__ __launch_bounds__(256) void k_pre(const float* __restrict__ W) {
    __shared__ float sr8[8], ss8[8];
    __shared__ float s_sc[2];
    int t = threadIdx.x, lane = t & 31, w = t >> 5;

    float tr = 0.f, ts = 0.f;
    #pragma unroll
    for (int q = 0; q < 8; q++) {
        tr += g_diag[t + 256 * q];
        ts += g_rowsum[t + 256 * q];
    }
    #pragma unroll
    for (int off = 16; off; off >>= 1) {
        tr += __shfl_xor_sync(0xffffffffu, tr, off);
        ts += __shfl_xor_sync(0xffffffffu, ts, off);
    }
    if (lane == 0) { sr8[w] = tr; ss8[w] = ts; }
    __syncthreads();
    if (t == 0) {
        float a = 0.f, b = 0.f;
        #pragma unroll
        for (int q = 0; q < 8; q++) { a += sr8[q]; b += ss8[q]; }
        s_sc[0] = a; s_sc[1] = b;
    }
    __syncthreads();
    float trv = s_sc[0], tsv = s_sc[1];

    int il = t >> 2, c4 = t & 3;
    int i = blockIdx.x * 64 + il;
    float di = g_diag[i], ri = g_rowsum[i], ci = g_colsum[i];

    float4 w0  = *(const float4*)(W + 0*16  + c4*4);
    float4 w1  = *(const float4*)(W + 1*16  + c4*4);
    float4 w2  = *(const float4*)(W + 2*16  + c4*4);
    float4 w3  = *(const float4*)(W + 3*16  + c4*4);
    float4 w4  = *(const float4*)(W + 4*16  + c4*4);
    float4 w5  = *(const float4*)(W + 5*16  + c4*4);
    float4 w6  = *(const float4*)(W + 6*16  + c4*4);
    float4 w7  = *(const float4*)(W + 7*16  + c4*4);
    float4 w8  = *(const float4*)(W + 8*16  + c4*4);
    float4 w9  = *(const float4*)(W + 9*16  + c4*4);
    float4 w10 = *(const float4*)(W + 10*16 + c4*4);
    float4 w13 = *(const float4*)(W + 13*16 + c4*4);
    float4 w14 = *(const float4*)(W + 14*16 + c4*4);

    float4 rf, cc, dd;
    rf.x = fmaf(di,w8.x, fmaf(ri,w9.x, fmaf(ci,w10.x, fmaf(trv,w13.x, tsv*w14.x))));
    rf.y = fmaf(di,w8.y, fmaf(ri,w9.y, fmaf(ci,w10.y, fmaf(trv,w13.y, tsv*w14.y))));
    rf.z = fmaf(di,w8.z, fmaf(ri,w9.z, fmaf(ci,w10.z, fmaf(trv,w13.z, tsv*w14.z))));
    rf.w = fmaf(di,w8.w, fmaf(ri,w9.w, fmaf(ci,w10.w, fmaf(trv,w13.w, tsv*w14.w))));
    cc.x = fmaf(di,w5.x, fmaf(ri,w6.x, ci*w7.x));
    cc.y = fmaf(di,w5.y, fmaf(ri,w6.y, ci*w7.y));
    cc.z = fmaf(di,w5.z, fmaf(ri,w6.z, ci*w7.z));
    cc.w = fmaf(di,w5.w, fmaf(ri,w6.w, ci*w7.w));
    dd.x = fmaf(di,w0.x, fmaf(ri,w1.x, fmaf(ci,w2.x, fmaf(trv,w3.x, tsv*w4.x))));
    dd.y = fmaf(di,w0.y, fmaf(ri,w1.y, fmaf(ci,w2.y, fmaf(trv,w3.y, tsv*w4.y))));
    dd.z = fmaf(di,w0.z, fmaf(ri,w1.z, fmaf(ci,w2.z, fmaf(trv,w3.z, tsv*w4.z))));
    dd.w = fmaf(di,w0.w, fmaf(ri,w1.w, fmaf(ci,w2.w, fmaf(trv,w3.w, tsv*w4.w))));

    *(float4*)(g_Rf + i*OUTC + c4*4) = rf;
    *(float4*)(g_Cc + i*OUTC + c4*4) = cc;
    *(float4*)(g_Dd + i*OUTC + c4*4) = dd;
}

// ---------------------------------------------------------------------------
__device__ __forceinline__ float4 f4add(float4 a, float4 b) {
    return make_float4(a.x + b.x, a.y + b.y, a.z + b.z, a.w + b.w);
}
__device__ __forceinline__ float4 f4fma(float s, float4 w, float4 acc) {
    return make_float4(fmaf(s, w.x, acc.x), fmaf(s, w.y, acc.y),
                       fmaf(s, w.z, acc.z), fmaf(s, w.w, acc.w));
}

// 32x32 output tile per block. Lane layout: lane = jsub*4 + c4 so every
// STG.128 / Cc LDG.128 is a fully-contiguous 512B warp transaction.
__global__ __launch_bounds__(256, 4) void k_main(const float* __restrict__ A,
                                                 const float* __restrict__ W,
                                                 float* __restrict__ out) {
    __shared__ float sT[32][33];      // A[j][i] tile (transposed source)
    __shared__ float sA[32][33];      // A[i][j] tile
    __shared__ float4 sw11[4], sw12[4];
    int t = threadIdx.x;
    int j0 = blockIdx.x * 32, i0 = blockIdx.y * 32;

    if (t < 4)      sw11[t]     = *(const float4*)(W + 11*16 + t*4);
    else if (t < 8) sw12[t - 4] = *(const float4*)(W + 12*16 + (t-4)*4);

    #pragma unroll
    for (int k = 0; k < 4; k++) {
        int e = t + 256 * k;
        int r = e >> 5, c = e & 31;
        sT[r][c] = A[(size_t)(j0 + r) * NN + i0 + c];   // rows j0.., cols i0..
        sA[r][c] = A[(size_t)(i0 + r) * NN + j0 + c];   // rows i0.., cols j0..
    }
    __syncthreads();

    int wi = t >> 5, lane = t & 31;
    int jsub = lane >> 2, c4 = lane & 3;
    float4 w11c = sw11[c4], w12c = sw12[c4];

    // warp's i range: i0 + wi*4 .. +3 ; hoist Rf chunks (broadcast loads)
    float4 rf[4];
    #pragma unroll
    for (int k = 0; k < 4; k++)
        rf[k] = *(const float4*)(g_Rf + (size_t)(i0 + wi*4 + k) * OUTC + c4*4);

    #pragma unroll
    for (int jg = 0; jg < 4; jg++) {
        int jj = jg * 8 + jsub;
        int j  = j0 + jj;
        float4 cc = *(const float4*)(g_Cc + (size_t)j * OUTC + c4*4);  // coalesced

        #pragma unroll
        for (int k = 0; k < 4; k++) {
            int ii = wi * 4 + k;
            int i  = i0 + ii;
            float av = sA[ii][jj];
            float tv = sT[jj][ii];
            float4 o = f4fma(av, w12c, f4fma(tv, w11c, f4add(rf[k], cc)));
            if (i == j)
                o = f4add(o, *(const float4*)(g_Dd + (size_t)i * OUTC + c4*4));
            *(float4*)(out + ((size_t)i * NN + j) * OUTC + c4*4) = o;   // coalesced
        }
    }
}

extern "C" void kernel_launch(void* const* d_in, const int* in_sizes, int n_in,
                              void* d_out, int out_size) {
    const float* A = (const float*)d_in[0];
    const float* W = (const float*)d_in[1];
    float* out = (float*)d_out;

    k_rowcol<<<320, 256>>>(A);
    k_pre<<<32, 256>>>(W);
    k_main<<<dim3(64, 64), 256>>>(A, W, out);
}